// round 8
// baseline (speedup 1.0000x reference)
#include <cuda_runtime.h>

// NetNew_17162689315115 — R8: dual-port weight sourcing.
// Layers 0-5 + Wf from SHARED (LDS.128 broadcast, padded rows);
// layers 6-7 from CONSTANT (LDC, exact rows with peel/tail).
// Relieves the half-rate constant port (R7's binder); FMA pipe now binds.
// h[84] register-resident, fully unrolled; accumulation order == R1.

struct NetParams {
    const float* x;
    float*       out;
    int          B;
};
struct PrepParams {
    const float* W[9];   // W1..W8, Wf
};

// ---- shared-side layers 0..5 (padded rows) ----
template <int L> struct SC {
    static constexpr int DIN  = 8 + 9 * L;
    static constexpr int DP   = (DIN + 3) & ~3;
    static constexpr int BASE = 72 - 9 * L;
};
template <int L> struct SOff;
template <> struct SOff<0> { static constexpr int V = 0; };
template <int L> struct SOff {
    static constexpr int V = SOff<L - 1>::V + 13 * SC<L - 1>::DP;
};
static constexpr int WF_SOFF   = SOff<5>::V + 13 * SC<5>::DP;   // 2496
static constexpr int SM_FLOATS = WF_SOFF + 80;                  // 2576 (10.3KB)

// ---- const-side layers 6..7 (exact rows) ----
template <int L> struct CCfg;
template <> struct CCfg<6> { static constexpr int DIN = 62, BASE = 18, OFF = 0; };
template <> struct CCfg<7> { static constexpr int DIN = 71, BASE = 9,  OFF = 13 * 62; };
static constexpr int CW_TOTAL = 13 * 62 + 13 * 71;              // 1729

// staging scratch: [0, CW_TOTAL) const part, then (aligned) shared part
static constexpr int SH_GOFF  = (CW_TOTAL + 3) & ~3;            // 1732
static constexpr int G_TOTAL  = SH_GOFF + SM_FLOATS;

__constant__ __align__(16) float cw[CW_TOTAL];
__device__   __align__(16) float g_wpad[G_TOTAL];

__device__ __forceinline__ float clip_mag(float v, float mx) {
    if (fabsf(v) >= mx) v = v * fabsf(mx / v);
    return v;
}

// ---- prep kernel: pack both regions ----
__global__ void netnew_prep(PrepParams pp) {
    // const region: layers 6,7 exact row-major
    {
        const float* g6 = pp.W[6];
        for (int i = threadIdx.x; i < 13 * 62; i += blockDim.x)
            g_wpad[CCfg<6>::OFF + i] = g6[i];
        const float* g7 = pp.W[7];
        for (int i = threadIdx.x; i < 13 * 71; i += blockDim.x)
            g_wpad[CCfg<7>::OFF + i] = g7[i];
    }
    // shared region: layers 0..5 padded rows + Wf
#define STAGE_S(L)                                                            \
    {                                                                         \
        constexpr int D  = SC<L>::DIN;                                        \
        constexpr int DP = SC<L>::DP;                                         \
        const float* g = pp.W[L];                                             \
        for (int i = threadIdx.x; i < 13 * DP; i += blockDim.x) {             \
            int r = i / DP, c = i - r * DP;                                   \
            g_wpad[SH_GOFF + SOff<L>::V + i] = (c < D) ? g[r * D + c] : 0.0f; \
        }                                                                     \
    }
    STAGE_S(0) STAGE_S(1) STAGE_S(2) STAGE_S(3) STAGE_S(4) STAGE_S(5)
#undef STAGE_S
    for (int i = threadIdx.x; i < 80; i += blockDim.x)
        g_wpad[SH_GOFF + WF_SOFF + i] = pp.W[8][i];
}

// ---- elementwise epilogue (identical order to R1) ----
__device__ __forceinline__ void apply_ops(const float* __restrict__ z,
                                          float* __restrict__ o) {
    o[0] = z[0] + z[1];
    o[1] = z[2] - z[3];
    o[2] = clip_mag(z[4] * z[5], 99999999.0f);
    {
        float b   = z[7];
        float den = (b == 0.0f) ? (b + 0.0001f) : b;
        o[3] = clip_mag(z[6] / den, 9999.0f);
    }
    o[4] = sinf(z[8]);
    o[5] = cosf(z[9]);
    {
        float a = z[10];
        if (a >= 17.0f) a = a * (17.0f / a);
        o[6] = expf(a);
    }
    o[7] = logf(fabsf(z[11]));
    o[8] = clip_mag(z[12] * z[12], 99999999.0f);
}

template <int L>
__device__ __forceinline__ void do_layer_smem(float* __restrict__ h,
                                              const float* __restrict__ smw) {
    constexpr int DP   = SC<L>::DP;
    constexpr int BASE = SC<L>::BASE;
    const float* wl = smw + SOff<L>::V;

    float z[13];
#pragma unroll
    for (int j = 0; j < 13; ++j) {
        float acc = 0.0f;
#pragma unroll
        for (int k = 0; k < DP; k += 4) {
            const float4 w = *reinterpret_cast<const float4*>(wl + j * DP + k);
            acc = fmaf(w.x, h[BASE + k + 0], acc);
            acc = fmaf(w.y, h[BASE + k + 1], acc);
            acc = fmaf(w.z, h[BASE + k + 2], acc);
            acc = fmaf(w.w, h[BASE + k + 3], acc);
        }
        z[j] = acc;
    }
    apply_ops(z, h + (BASE - 9));
}

template <int L>
__device__ __forceinline__ void do_layer_const(float* __restrict__ h) {
    constexpr int DIN  = CCfg<L>::DIN;
    constexpr int BASE = CCfg<L>::BASE;

    float z[13];
#pragma unroll
    for (int j = 0; j < 13; ++j) {
        const int roff = CCfg<L>::OFF + j * DIN;  // compile-time after unroll
        float acc = 0.0f;
        int k = 0;
        const int mis = roff & 3;
        if (mis != 0) {
            const int peel = 4 - mis;
#pragma unroll
            for (int t = 0; t < 3; ++t) {
                if (t < peel && k < DIN) {
                    acc = fmaf(cw[roff + k], h[BASE + k], acc);
                    ++k;
                }
            }
        }
#pragma unroll
        for (; k + 3 < DIN; k += 4) {
            const float4 w = *reinterpret_cast<const float4*>(cw + roff + k);
            acc = fmaf(w.x, h[BASE + k + 0], acc);
            acc = fmaf(w.y, h[BASE + k + 1], acc);
            acc = fmaf(w.z, h[BASE + k + 2], acc);
            acc = fmaf(w.w, h[BASE + k + 3], acc);
        }
#pragma unroll
        for (; k < DIN; ++k)
            acc = fmaf(cw[roff + k], h[BASE + k], acc);
        z[j] = acc;
    }
    apply_ops(z, h + (BASE - 9));
}

__global__ __launch_bounds__(96, 7)
void netnew_kernel8(NetParams p) {
    __shared__ __align__(16) float smw[SM_FLOATS];

    // stage shared region from packed global scratch (coalesced, L2-hot)
    for (int i = threadIdx.x; i < SM_FLOATS; i += 96)
        smw[i] = g_wpad[SH_GOFF + i];
    __syncthreads();

    const int row = blockIdx.x * blockDim.x + threadIdx.x;
    if (row >= p.B) return;

    // h: [outs8|...|outs1|x], x at [72..79], pads [80..83]=0 for padded reads
    float h[84];
    {
        const float4* xr = reinterpret_cast<const float4*>(p.x + (size_t)row * 8);
        float4 a = xr[0], b = xr[1];
        h[72] = a.x; h[73] = a.y; h[74] = a.z; h[75] = a.w;
        h[76] = b.x; h[77] = b.y; h[78] = b.z; h[79] = b.w;
        h[80] = 0.0f; h[81] = 0.0f; h[82] = 0.0f; h[83] = 0.0f;
    }

    do_layer_smem<0>(h, smw);
    do_layer_smem<1>(h, smw);
    do_layer_smem<2>(h, smw);
    do_layer_smem<3>(h, smw);
    do_layer_smem<4>(h, smw);
    do_layer_smem<5>(h, smw);
    do_layer_const<6>(h);
    do_layer_const<7>(h);

    // final: out = dot(Wf, h[0..79]) from shared, sequential ascending k
    float acc = 0.0f;
#pragma unroll
    for (int k = 0; k < 80; k += 4) {
        const float4 w = *reinterpret_cast<const float4*>(smw + WF_SOFF + k);
        acc = fmaf(w.x, h[k + 0], acc);
        acc = fmaf(w.y, h[k + 1], acc);
        acc = fmaf(w.z, h[k + 2], acc);
        acc = fmaf(w.w, h[k + 3], acc);
    }
    p.out[row] = acc;
}

extern "C" void kernel_launch(void* const* d_in, const int* in_sizes, int n_in,
                              void* d_out, int out_size) {
    PrepParams pp;
    for (int i = 0; i < 9; ++i) pp.W[i] = (const float*)d_in[1 + i];

    NetParams p;
    p.x   = (const float*)d_in[0];
    p.out = (float*)d_out;
    p.B   = in_sizes[0] / 8;

    netnew_prep<<<1, 256>>>(pp);

    void* src = nullptr;
    cudaGetSymbolAddress(&src, g_wpad);
    cudaMemcpyToSymbolAsync(cw, src, CW_TOTAL * sizeof(float), 0,
                            cudaMemcpyDeviceToDevice, 0);

    const int threads = 96;
    const int blocks  = (p.B + threads - 1) / threads;
    netnew_kernel8<<<blocks, threads>>>(p);
}

// round 9
// speedup vs baseline: 1.0689x; 1.0689x over previous
#include <cuda_runtime.h>

// NetNew_17162689315115 — R9: R7 (all weights in __constant__, exact rows,
// LDC.128 + peel/tail) with: (a) launch_bounds(128,6) -> 24 warps/SM,
// (b) no prep kernel: constant image is W1..W8,Wf concatenated, loaded by
// 9 direct D2D cudaMemcpyToSymbolAsync calls. Numerics identical to R7/R1.

struct NetParams {
    const float* x;
    float*       out;
    int          B;
};

template <int L> struct LC {
    static constexpr int DIN  = 8 + 9 * L;
    static constexpr int BASE = 72 - 9 * L;   // first input feature index
};
template <int L> struct WOff;
template <> struct WOff<0> { static constexpr int V = 0; };
template <int L> struct WOff {
    static constexpr int V = WOff<L - 1>::V + 13 * LC<L - 1>::DIN;
};
static constexpr int WF_OFF   = WOff<7>::V + 13 * LC<7>::DIN;  // 4108
static constexpr int CW_TOTAL = WF_OFF + 80;                   // 4188

__constant__ __align__(16) float cw[CW_TOTAL];

__device__ __forceinline__ float clip_mag(float v, float mx) {
    // matches jnp.where(|v| >= mx, v * |mx/v|, v) incl. inf -> NaN edge case
    if (fabsf(v) >= mx) v = v * fabsf(mx / v);
    return v;
}

template <int L>
__device__ __forceinline__ void do_layer(float* __restrict__ h) {
    constexpr int DIN  = LC<L>::DIN;
    constexpr int BASE = LC<L>::BASE;

    float z[13];
#pragma unroll
    for (int j = 0; j < 13; ++j) {
        const int roff = WOff<L>::V + j * DIN;   // compile-time after unroll
        float acc = 0.0f;
        int k = 0;
        const int mis = roff & 3;                // compile-time per j
        if (mis != 0) {
            const int peel = 4 - mis;
#pragma unroll
            for (int t = 0; t < 3; ++t) {
                if (t < peel && k < DIN) {
                    acc = fmaf(cw[roff + k], h[BASE + k], acc);
                    ++k;
                }
            }
        }
#pragma unroll
        for (; k + 3 < DIN; k += 4) {
            const float4 w = *reinterpret_cast<const float4*>(cw + roff + k);
            acc = fmaf(w.x, h[BASE + k + 0], acc);
            acc = fmaf(w.y, h[BASE + k + 1], acc);
            acc = fmaf(w.z, h[BASE + k + 2], acc);
            acc = fmaf(w.w, h[BASE + k + 3], acc);
        }
#pragma unroll
        for (; k < DIN; ++k)
            acc = fmaf(cw[roff + k], h[BASE + k], acc);
        z[j] = acc;
    }

    float* o = h + (BASE - 9);
    o[0] = z[0] + z[1];
    o[1] = z[2] - z[3];
    o[2] = clip_mag(z[4] * z[5], 99999999.0f);
    {
        float b   = z[7];
        float den = (b == 0.0f) ? (b + 0.0001f) : b;
        o[3] = clip_mag(z[6] / den, 9999.0f);
    }
    o[4] = sinf(z[8]);
    o[5] = cosf(z[9]);
    {
        float a = z[10];
        if (a >= 17.0f) a = a * (17.0f / a);
        o[6] = expf(a);
    }
    o[7] = logf(fabsf(z[11]));
    o[8] = clip_mag(z[12] * z[12], 99999999.0f);
}

__global__ __launch_bounds__(128, 6)
void netnew_kernel9(NetParams p) {
    const int row = blockIdx.x * blockDim.x + threadIdx.x;
    if (row >= p.B) return;

    // h layout: [outs8 | outs7 | ... | outs1 | x]; x at [72..79].
    float h[80];
    {
        const float4* xr = reinterpret_cast<const float4*>(p.x + (size_t)row * 8);
        float4 a = xr[0], b = xr[1];
        h[72] = a.x; h[73] = a.y; h[74] = a.z; h[75] = a.w;
        h[76] = b.x; h[77] = b.y; h[78] = b.z; h[79] = b.w;
    }

    do_layer<0>(h);
    do_layer<1>(h);
    do_layer<2>(h);
    do_layer<3>(h);
    do_layer<4>(h);
    do_layer<5>(h);
    do_layer<6>(h);
    do_layer<7>(h);

    // final: out = dot(Wf, h[0..79]), sequential ascending k (WF_OFF%4==0)
    float acc = 0.0f;
#pragma unroll
    for (int k = 0; k < 80; k += 4) {
        const float4 w = *reinterpret_cast<const float4*>(cw + WF_OFF + k);
        acc = fmaf(w.x, h[k + 0], acc);
        acc = fmaf(w.y, h[k + 1], acc);
        acc = fmaf(w.z, h[k + 2], acc);
        acc = fmaf(w.w, h[k + 3], acc);
    }
    p.out[row] = acc;
}

extern "C" void kernel_launch(void* const* d_in, const int* in_sizes, int n_in,
                              void* d_out, int out_size) {
    NetParams p;
    p.x   = (const float*)d_in[0];
    p.out = (float*)d_out;
    p.B   = in_sizes[0] / 8;

    // Constant image = W1..W8 (exact row-major) ++ Wf, at compile-time offsets.
    // Direct D2D copies into the symbol — no prep kernel needed.
    static const int sizes[9] = {
        13 * 8, 13 * 17, 13 * 26, 13 * 35, 13 * 44, 13 * 53, 13 * 62, 13 * 71, 80
    };
    size_t off = 0;
    for (int i = 0; i < 9; ++i) {
        cudaMemcpyToSymbolAsync(cw, d_in[1 + i], sizes[i] * sizeof(float),
                                off, cudaMemcpyDeviceToDevice, 0);
        off += sizes[i] * sizeof(float);
    }

    const int threads = 128;
    const int blocks  = (p.B + threads - 1) / threads;
    netnew_kernel9<<<blocks, threads>>>(p);
}